// round 14
// baseline (speedup 1.0000x reference)
#include <cuda_runtime.h>
#include <cuda_fp16.h>
#include <cstdint>

#define BB 2
#define NN 2048
#define DD 64
#define AAN 16
#define EE 2
#define TT 5
#define HH 128
#define EN (EE*NN)       /* 4096 */
#define ADJW (2*EN)      /* 8192 */
#define KSPL 4
#define KLEN (EN/KSPL)   /* 1024 */
#define KCH  (KLEN/32)   /* 32 chunks of K=32 */
#define TILEH 131072     /* halves per adjT tile: 32*128*32 */

// ---------------- device scratch (no allocation allowed) ----------------
__device__ __half g_adjT[(size_t)BB*2*KSPL*16*TILEH];  // tiled fp16 adj, chunk-major (8KB/chunk)
__device__ float  g_h[BB*NN*DD];
__device__ __half g_msgT[2*BB*KSPL*32*64*32];          // [dir][b][ks][chunk][d][32] (4KB/chunk)
__device__ float  g_ain[KSPL*BB*NN*DD];                // K-split partials (fp32)
__device__ float  g_aout[KSPL*BB*NN*DD];

__device__ __forceinline__ float sigf(float x){ return 1.0f/(1.0f+__expf(-x)); }
__device__ __forceinline__ uint32_t s2u(const void* p){
    uint32_t a; asm("{ .reg .u64 t; cvta.to.shared.u64 t, %1; cvt.u32.u64 %0, t; }":"=r"(a):"l"(p)); return a;
}
__device__ __forceinline__ void cpbulk(uint32_t dst, const void* src, uint32_t bytes, uint32_t mbar){
    asm volatile("cp.async.bulk.shared::cta.global.mbarrier::complete_tx::bytes [%0], [%1], %2, [%3];"
        ::"r"(dst),"l"(src),"r"(bytes),"r"(mbar):"memory");
}
__device__ __forceinline__ void mb_init(uint32_t a, uint32_t c){
    asm volatile("mbarrier.init.shared.b64 [%0], %1;"::"r"(a),"r"(c):"memory");
}
__device__ __forceinline__ void mb_expect(uint32_t a, uint32_t tx){
    asm volatile("mbarrier.arrive.expect_tx.shared.b64 _, [%0], %1;"::"r"(a),"r"(tx):"memory");
}
__device__ __forceinline__ void mb_wait(uint32_t mbar, uint32_t parity){
    uint32_t done;
    asm volatile("{\n\t.reg .pred p;\n\t"
        "mbarrier.try_wait.parity.acquire.cta.shared::cta.b64 p, [%1], %2;\n\t"
        "selp.b32 %0, 1, 0, p;\n\t}":"=r"(done):"r"(mbar),"r"(parity):"memory");
    while(!done){
        asm volatile("{\n\t.reg .pred p;\n\t"
            "mbarrier.try_wait.parity.acquire.cta.shared::cta.b64 p, [%1], %2, 0x989680;\n\t"
            "selp.b32 %0, 1, 0, p;\n\t}":"=r"(done):"r"(mbar),"r"(parity):"memory");
    }
}
__device__ __forceinline__ void ldsm4(uint32_t& r0, uint32_t& r1, uint32_t& r2, uint32_t& r3, uint32_t a){
    asm volatile("ldmatrix.sync.aligned.m8n8.x4.shared.b16 {%0,%1,%2,%3}, [%4];"
                 : "=r"(r0),"=r"(r1),"=r"(r2),"=r"(r3) : "r"(a));
}
__device__ __forceinline__ void mma16(float* c, const uint32_t* a, const uint32_t* b){
    asm volatile("mma.sync.aligned.m16n8k16.row.col.f32.f16.f16.f32 "
                 "{%0,%1,%2,%3},{%4,%5,%6,%7},{%8,%9},{%0,%1,%2,%3};"
                 : "+f"(c[0]),"+f"(c[1]),"+f"(c[2]),"+f"(c[3])
                 : "r"(a[0]),"r"(a[1]),"r"(a[2]),"r"(a[3]),"r"(b[0]),"r"(b[1]));
}

// ---------------- init ----------------
__global__ void k_init(const float4* __restrict__ ps) {
    int i = blockIdx.x*256 + threadIdx.x;
    ((float4*)g_h)[i] = ps[i];
}

// ---------------- round + tile-permute: adj fp32 -> g_adjT fp16 chunk-major tiles ----------------
__global__ void k_roundT(const float* __restrict__ adj) {
    int mt = blockIdx.x, dir = blockIdx.y;
    int b = blockIdx.z >> 2, ks = blockIdx.z & 3;
    int tid = threadIdx.x;
    const float* src = adj + ((size_t)(b*NN + mt*128))*ADJW + dir*EN + ks*KLEN;
    __half* dstT = g_adjT + ((size_t)(((b*2 + dir)*KSPL + ks)*16 + mt))*TILEH;
    for (int i = 0; i < 128; i++) {
        int idx = tid + i*256;          // 0..32767 float4 positions
        int r = idx >> 8, c4 = idx & 255;
        float4 v = *(const float4*)(src + (size_t)r*ADJW + c4*4);
        __half2 h01 = __floats2half2_rn(v.x, v.y);
        __half2 h23 = __floats2half2_rn(v.z, v.w);
        uint2 pk = make_uint2(*(uint32_t*)&h01, *(uint32_t*)&h23);
        *(uint2*)(dstT + (c4 >> 3)*4096 + r*32 + (c4 & 7)*4) = pk;
    }
}

// ---------------- transform: msgT chunk-major = fp16( h@W_io[e] + b_io[e] ) ----------------
__global__ void k_transform(const float* __restrict__ Win, const float* __restrict__ bin,
                            const float* __restrict__ Wout, const float* __restrict__ bout) {
    __shared__ float sh[32*65];
    __shared__ float sWi[64*64], sWo[64*64];
    __shared__ float sbi[64], sbo[64];
    int nt = blockIdx.x, e = blockIdx.y, b = blockIdx.z;
    int tid = threadIdx.x;

    const float4* h4 = (const float4*)(g_h + (b*NN + nt*32)*64);
    #pragma unroll
    for (int i = 0; i < 2; i++) {
        float4 v = h4[tid + i*256];
        int idx = (tid + i*256)*4;
        int r = idx >> 6, c = idx & 63;
        sh[r*65 + c]   = v.x;
        sh[r*65 + c+1] = v.y;
        sh[r*65 + c+2] = v.z;
        sh[r*65 + c+3] = v.w;
    }
    const float4* wi4 = (const float4*)(Win + e*4096);
    const float4* wo4 = (const float4*)(Wout + e*4096);
    #pragma unroll
    for (int i = 0; i < 4; i++) {
        ((float4*)sWi)[tid + i*256] = wi4[tid + i*256];
        ((float4*)sWo)[tid + i*256] = wo4[tid + i*256];
    }
    if (tid < 64) { sbi[tid] = bin[e*64 + tid]; sbo[tid] = bout[e*64 + tid]; }
    __syncthreads();

    int rg = tid & 7;          // rows rg*4 .. rg*4+3 (m within chunk)
    int cp = tid >> 3;         // cols cp, cp+32 (d)
    float ai[4][2], ao[4][2];
    #pragma unroll
    for (int i = 0; i < 4; i++) {
        ai[i][0] = sbi[cp];    ai[i][1] = sbi[cp+32];
        ao[i][0] = sbo[cp];    ao[i][1] = sbo[cp+32];
    }
    #pragma unroll 4
    for (int k = 0; k < 64; k++) {
        float wi0 = sWi[k*64 + cp], wi1 = sWi[k*64 + cp + 32];
        float wo0 = sWo[k*64 + cp], wo1 = sWo[k*64 + cp + 32];
        #pragma unroll
        for (int i = 0; i < 4; i++) {
            float hv = sh[(rg*4 + i)*65 + k];
            ai[i][0] += hv*wi0; ai[i][1] += hv*wi1;
            ao[i][0] += hv*wo0; ao[i][1] += hv*wo1;
        }
    }
    int chg = e*64 + nt;             // global chunk id 0..127
    int ks = chg >> 5, cc = chg & 31;
    #pragma unroll
    for (int io = 0; io < 2; io++) {
        __half* dst = g_msgT + ((size_t)((io*BB + b)*KSPL + ks))*65536 + cc*2048;
        float (*ac)[2] = io ? ao : ai;
        #pragma unroll
        for (int j = 0; j < 2; j++) {
            int d = cp + j*32;
            __half2 p0 = __floats2half2_rn(ac[0][j], ac[1][j]);
            __half2 p1 = __floats2half2_rn(ac[2][j], ac[3][j]);
            uint2 pk = make_uint2(*(uint32_t*)&p0, *(uint32_t*)&p1);
            *(uint2*)(dst + d*32 + rg*4) = pk;
        }
    }
}

// ---------------- GEMM fp16 via cp.async.bulk: 2 bulk ops/chunk ----------------
// grid (16,2,8)=256 CTAs, 256 thr, K-chunk 32, NSTG=4
#define STGB 12288                 /* A 8192 + B 4096 */
#define NSTG 4
#define MB_OFF (NSTG*STGB)
#define SMEM_GEMM (MB_OFF + 64)

__global__ __launch_bounds__(256, 3) void k_gemm() {
    extern __shared__ char smc[];
    uint32_t usm = s2u(smc);
    uint32_t mb = usm + MB_OFF;
    int tid = threadIdx.x;
    int wid = tid >> 5, lane = tid & 31;
    int lr = lane >> 2, lc = lane & 3;
    int wm = wid & 3, wn = wid >> 2;
    int mt = blockIdx.x, dir = blockIdx.y;
    int b = blockIdx.z >> 2, ks = blockIdx.z & 3;
    int m0 = mt * 128;

    const __half* aBase = g_adjT + ((size_t)(((b*2 + dir)*KSPL + ks)*16 + mt))*TILEH;
    const __half* bBase = g_msgT + ((size_t)((dir*BB + b)*KSPL + ks))*65536;

    if (tid == 0) {
        #pragma unroll
        for (int s = 0; s < NSTG; s++) mb_init(mb + s*8, 1);
    }
    __syncthreads();

    uint32_t aOff = (uint32_t)((wm*32 + (lane & 15))*64 + (lane >> 4)*16);
    uint32_t bOff = (uint32_t)(8192 + (wn*32 + ((lane >> 4)*8) + (lane & 7))*64 + ((lane >> 3) & 1)*16);

    auto fill = [&](int stage, int c) {
        uint32_t sb = usm + stage*STGB;
        mb_expect(mb + stage*8, STGB);
        cpbulk(sb, aBase + (size_t)c*4096, 8192, mb + stage*8);
        cpbulk(sb + 8192, bBase + (size_t)c*2048, 4096, mb + stage*8);
    };

    if (tid == 0) { fill(0,0); fill(1,1); fill(2,2); }

    float acc[2][4][4];
    #pragma unroll
    for (int i = 0; i < 2; i++)
        #pragma unroll
        for (int j = 0; j < 4; j++)
            #pragma unroll
            for (int q = 0; q < 4; q++) acc[i][j][q] = 0.f;

    for (int c = 0; c < KCH; c++) {
        int st = c & 3;
        __syncthreads();                 // all warps done with stage (c+3)&3's previous phase
        if (tid == 0 && c + 3 < KCH) fill((c + 3) & 3, c + 3);
        mb_wait(mb + st*8, (c >> 2) & 1);

        uint32_t sb = usm + st*STGB;
        #pragma unroll
        for (int k16 = 0; k16 < 2; k16++) {
            uint32_t af[2][4], bf[4][2];
            #pragma unroll
            for (int mf = 0; mf < 2; mf++)
                ldsm4(af[mf][0], af[mf][1], af[mf][2], af[mf][3],
                      sb + aOff + mf*1024 + k16*32);
            #pragma unroll
            for (int bg = 0; bg < 2; bg++) {
                uint32_t r0, r1, r2, r3;
                ldsm4(r0, r1, r2, r3, sb + bOff + bg*1024 + k16*32);
                bf[bg*2][0] = r0;   bf[bg*2][1] = r1;
                bf[bg*2+1][0] = r2; bf[bg*2+1][1] = r3;
            }
            #pragma unroll
            for (int mf = 0; mf < 2; mf++)
                #pragma unroll
                for (int nf = 0; nf < 4; nf++)
                    mma16(acc[mf][nf], af[mf], bf[nf]);
        }
    }

    float* dst = (dir ? g_aout : g_ain) + (size_t)ks*BB*NN*DD + (size_t)b*NN*64;
    #pragma unroll
    for (int mf = 0; mf < 2; mf++) {
        #pragma unroll
        for (int nf = 0; nf < 4; nf++) {
            int row = m0 + wm*32 + mf*16 + lr;
            int colg = wn*32 + nf*8 + lc*2;
            *(float2*)(dst + (size_t)row*64 + colg)     = make_float2(acc[mf][nf][0], acc[mf][nf][1]);
            *(float2*)(dst + (size_t)(row+8)*64 + colg) = make_float2(acc[mf][nf][2], acc[mf][nf][3]);
        }
    }
}

// ---------------- GRU: fp32 weights smem-staged; sums the K-split partials ----------------
#define GRU_WR 0
#define GRU_WZ 12288
#define GRU_WH 24576
#define GRU_SA 36864              /* 32*192 */
#define GRU_RH 43008              /* 32*64  */
#define SMEM_GRU ((GRU_RH + 2048)*4)   /* 180224 B */

__global__ __launch_bounds__(512, 1) void k_gru(
        const float* __restrict__ Wr, const float* __restrict__ br,
        const float* __restrict__ Wz, const float* __restrict__ bz,
        const float* __restrict__ Wh, const float* __restrict__ bh) {
    extern __shared__ float smf[];
    int nt = blockIdx.x, b = blockIdx.y;
    int tid = threadIdx.x;
    int n0 = nt * 32;

    #pragma unroll
    for (int i = 0; i < 6; i++) {
        int idx = tid + i*512;
        ((float4*)(smf + GRU_WR))[idx] = ((const float4*)Wr)[idx];
        ((float4*)(smf + GRU_WZ))[idx] = ((const float4*)Wz)[idx];
        ((float4*)(smf + GRU_WH))[idx] = ((const float4*)Wh)[idx];
    }
    const float* ain0  = g_ain  + (size_t)(b*NN + n0)*64;
    const float* aout0 = g_aout + (size_t)(b*NN + n0)*64;
    const float* hp    = g_h    + (size_t)(b*NN + n0)*64;
    const size_t PSTR = (size_t)BB*NN*DD;
    #pragma unroll
    for (int i = 0; i < 4; i++) {
        int idx = tid + i*512;
        int r = idx >> 6, c = idx & 63;
        float si = 0.f, so = 0.f;
        #pragma unroll
        for (int p = 0; p < KSPL; p++) {
            si += ain0[p*PSTR + r*64 + c];
            so += aout0[p*PSTR + r*64 + c];
        }
        smf[GRU_SA + r*192 + c]       = si;
        smf[GRU_SA + r*192 + 64 + c]  = so;
        smf[GRU_SA + r*192 + 128 + c] = hp[r*64 + c];
    }
    __syncthreads();

    int col = tid & 63, rg = tid >> 6;
    const float* sa = smf + GRU_SA;
    float accR[4], accZ[4];
    #pragma unroll
    for (int i = 0; i < 4; i++) { accR[i] = br[col]; accZ[i] = bz[col]; }
    #pragma unroll 8
    for (int k = 0; k < 192; k++) {
        float wr = smf[GRU_WR + k*64 + col];
        float wz = smf[GRU_WZ + k*64 + col];
        #pragma unroll
        for (int i = 0; i < 4; i++) {
            float v = sa[(rg*4 + i)*192 + k];
            accR[i] += v*wr; accZ[i] += v*wz;
        }
    }
    float zg[4], hold[4];
    #pragma unroll
    for (int i = 0; i < 4; i++) {
        int r = rg*4 + i;
        float rr = sigf(accR[i]);
        zg[i] = sigf(accZ[i]);
        hold[i] = sa[r*192 + 128 + col];
        smf[GRU_RH + r*64 + col] = rr * hold[i];
    }
    __syncthreads();

    float accH[4];
    #pragma unroll
    for (int i = 0; i < 4; i++) accH[i] = bh[col];
    #pragma unroll 8
    for (int k = 0; k < 128; k++) {
        float wh = smf[GRU_WH + k*64 + col];
        #pragma unroll
        for (int i = 0; i < 4; i++) accH[i] += sa[(rg*4 + i)*192 + k]*wh;
    }
    #pragma unroll 8
    for (int k = 0; k < 64; k++) {
        float wh = smf[GRU_WH + (128 + k)*64 + col];
        #pragma unroll
        for (int i = 0; i < 4; i++) accH[i] += smf[GRU_RH + (rg*4 + i)*64 + k]*wh;
    }
    float* hw = g_h + (size_t)(b*NN + n0)*64;
    #pragma unroll
    for (int i = 0; i < 4; i++) {
        int r = rg*4 + i;
        float hh = tanhf(accH[i]);
        hw[r*64 + col] = (1.0f - zg[i])*hold[i] + zg[i]*hh;
    }
}

// ---------------- readout ----------------
__global__ void k_out(const float* __restrict__ ann, const float* __restrict__ Wo1,
                      const float* __restrict__ bo1, const float* __restrict__ Wo2,
                      const float* __restrict__ bo2, float* __restrict__ out) {
    __shared__ float sx[4][80];
    __shared__ float sred[128];
    int blk = blockIdx.x;
    int b = blk >> 9;
    int n0 = (blk & 511) * 4;
    int tid = threadIdx.x;
    for (int i = tid; i < 256; i += 128) {
        int r = i >> 6, c = i & 63;
        sx[r][c] = g_h[(b*NN + n0 + r)*64 + c];
    }
    if (tid < 64) {
        int r = tid >> 4, c = tid & 15;
        sx[r][64 + c] = ann[(b*NN + n0 + r)*AAN + c];
    }
    __syncthreads();
    float v[4];
    float w2 = Wo2[tid], b1 = bo1[tid];
    #pragma unroll
    for (int r = 0; r < 4; r++) {
        float acc = b1;
        #pragma unroll 10
        for (int k = 0; k < 80; k++) acc += sx[r][k]*Wo1[k*128 + tid];
        v[r] = w2 * sigf(acc);
    }
    #pragma unroll
    for (int r = 0; r < 4; r++) {
        sred[tid] = v[r];
        __syncthreads();
        for (int s = 64; s > 0; s >>= 1) {
            if (tid < s) sred[tid] += sred[tid + s];
            __syncthreads();
        }
        if (tid == 0) out[b*NN + n0 + r] = sred[0] + bo2[0];
        __syncthreads();
    }
}

extern "C" void kernel_launch(void* const* d_in, const int* in_sizes, int n_in,
                              void* d_out, int out_size) {
    const float* prop = (const float*)d_in[0];
    const float* ann  = (const float*)d_in[1];
    const float* adj  = (const float*)d_in[2];
    const float* Win  = (const float*)d_in[3];
    const float* bin  = (const float*)d_in[4];
    const float* Wout = (const float*)d_in[5];
    const float* bout = (const float*)d_in[6];
    const float* Wr   = (const float*)d_in[7];
    const float* br   = (const float*)d_in[8];
    const float* Wz   = (const float*)d_in[9];
    const float* bz   = (const float*)d_in[10];
    const float* Wh   = (const float*)d_in[11];
    const float* bh   = (const float*)d_in[12];
    const float* Wo1  = (const float*)d_in[13];
    const float* bo1  = (const float*)d_in[14];
    const float* Wo2  = (const float*)d_in[15];
    const float* bo2  = (const float*)d_in[16];
    float* out = (float*)d_out;

    cudaFuncSetAttribute(k_gemm, cudaFuncAttributeMaxDynamicSharedMemorySize, SMEM_GEMM);
    cudaFuncSetAttribute(k_gru,  cudaFuncAttributeMaxDynamicSharedMemorySize, SMEM_GRU);

    k_init<<<256, 256>>>((const float4*)prop);
    k_roundT<<<dim3(16, 2, BB*KSPL), 256>>>(adj);
    for (int t = 0; t < TT; t++) {
        k_transform<<<dim3(64, EE, BB), 256>>>(Win, bin, Wout, bout);
        k_gemm<<<dim3(16, 2, BB*KSPL), 256, SMEM_GEMM>>>();
        k_gru<<<dim3(64, BB), 512, SMEM_GRU>>>(Wr, br, Wz, bz, Wh, bh);
    }
    k_out<<<1024, 128>>>(ann, Wo1, bo1, Wo2, bo2, out);
}

// round 15
// speedup vs baseline: 1.4027x; 1.4027x over previous
#include <cuda_runtime.h>
#include <cuda_fp16.h>
#include <cstdint>

#define BB 2
#define NN 2048
#define DD 64
#define AAN 16
#define EE 2
#define TT 5
#define HH 128
#define EN (EE*NN)       /* 4096 */
#define ADJW (2*EN)      /* 8192 */
#define KSPL 4
#define KLEN (EN/KSPL)   /* 1024 */
#define KCH  (KLEN/32)   /* 32 chunks of K=32 */
#define TILEH 131072     /* halves per adjT tile: 32*128*32 */

// ---------------- device scratch (no allocation allowed) ----------------
__device__ __half g_adjT[(size_t)BB*2*KSPL*16*TILEH];  // tiled fp16 adj, chunk-major (8KB/chunk)
__device__ float  g_h[BB*NN*DD];
__device__ __half g_msgT[2*BB*KSPL*32*64*32];          // [dir][b][ks][chunk][d][32] (4KB/chunk)
__device__ float  g_ain[KSPL*BB*NN*DD];                // K-split partials (fp32)
__device__ float  g_aout[KSPL*BB*NN*DD];

__device__ __forceinline__ float sigf(float x){ return 1.0f/(1.0f+__expf(-x)); }
__device__ __forceinline__ uint32_t s2u(const void* p){
    uint32_t a; asm("{ .reg .u64 t; cvta.to.shared.u64 t, %1; cvt.u32.u64 %0, t; }":"=r"(a):"l"(p)); return a;
}
__device__ __forceinline__ void cpa16(uint32_t d, const void* s){
    asm volatile("cp.async.cg.shared.global [%0], [%1], 16;"::"r"(d),"l"(s));
}
#define CPCOMMIT() asm volatile("cp.async.commit_group;":::"memory")
#define CPWAIT(n)  asm volatile("cp.async.wait_group %0;"::"n"(n):"memory")

__device__ __forceinline__ void ldsm4(uint32_t& r0, uint32_t& r1, uint32_t& r2, uint32_t& r3, uint32_t a){
    asm volatile("ldmatrix.sync.aligned.m8n8.x4.shared.b16 {%0,%1,%2,%3}, [%4];"
                 : "=r"(r0),"=r"(r1),"=r"(r2),"=r"(r3) : "r"(a));
}
__device__ __forceinline__ void mma16(float* c, const uint32_t* a, const uint32_t* b){
    asm volatile("mma.sync.aligned.m16n8k16.row.col.f32.f16.f16.f32 "
                 "{%0,%1,%2,%3},{%4,%5,%6,%7},{%8,%9},{%0,%1,%2,%3};"
                 : "+f"(c[0]),"+f"(c[1]),"+f"(c[2]),"+f"(c[3])
                 : "r"(a[0]),"r"(a[1]),"r"(a[2]),"r"(a[3]),"r"(b[0]),"r"(b[1]));
}

// ---------------- init ----------------
__global__ void k_init(const float4* __restrict__ ps) {
    int i = blockIdx.x*256 + threadIdx.x;
    ((float4*)g_h)[i] = ps[i];
}

// ---------------- round + tile-permute: adj fp32 -> g_adjT fp16 chunk-major tiles ----------------
__global__ void k_roundT(const float* __restrict__ adj) {
    int mt = blockIdx.x, dir = blockIdx.y;
    int b = blockIdx.z >> 2, ks = blockIdx.z & 3;
    int tid = threadIdx.x;
    const float* src = adj + ((size_t)(b*NN + mt*128))*ADJW + dir*EN + ks*KLEN;
    __half* dstT = g_adjT + ((size_t)(((b*2 + dir)*KSPL + ks)*16 + mt))*TILEH;
    for (int i = 0; i < 128; i++) {
        int idx = tid + i*256;          // 0..32767 float4 positions
        int r = idx >> 8, c4 = idx & 255;
        float4 v = *(const float4*)(src + (size_t)r*ADJW + c4*4);
        __half2 h01 = __floats2half2_rn(v.x, v.y);
        __half2 h23 = __floats2half2_rn(v.z, v.w);
        uint2 pk = make_uint2(*(uint32_t*)&h01, *(uint32_t*)&h23);
        *(uint2*)(dstT + (c4 >> 3)*4096 + r*32 + (c4 & 7)*4) = pk;
    }
}

// ---------------- transform: msgT chunk-major = fp16( h@W_io[e] + b_io[e] ) ----------------
__global__ void k_transform(const float* __restrict__ Win, const float* __restrict__ bin,
                            const float* __restrict__ Wout, const float* __restrict__ bout) {
    __shared__ float sh[32*65];
    __shared__ float sWi[64*64], sWo[64*64];
    __shared__ float sbi[64], sbo[64];
    int nt = blockIdx.x, e = blockIdx.y, b = blockIdx.z;
    int tid = threadIdx.x;

    const float4* h4 = (const float4*)(g_h + (b*NN + nt*32)*64);
    #pragma unroll
    for (int i = 0; i < 2; i++) {
        float4 v = h4[tid + i*256];
        int idx = (tid + i*256)*4;
        int r = idx >> 6, c = idx & 63;
        sh[r*65 + c]   = v.x;
        sh[r*65 + c+1] = v.y;
        sh[r*65 + c+2] = v.z;
        sh[r*65 + c+3] = v.w;
    }
    const float4* wi4 = (const float4*)(Win + e*4096);
    const float4* wo4 = (const float4*)(Wout + e*4096);
    #pragma unroll
    for (int i = 0; i < 4; i++) {
        ((float4*)sWi)[tid + i*256] = wi4[tid + i*256];
        ((float4*)sWo)[tid + i*256] = wo4[tid + i*256];
    }
    if (tid < 64) { sbi[tid] = bin[e*64 + tid]; sbo[tid] = bout[e*64 + tid]; }
    __syncthreads();

    int rg = tid & 7;          // rows rg*4 .. rg*4+3 (m within chunk)
    int cp = tid >> 3;         // cols cp, cp+32 (d)
    float ai[4][2], ao[4][2];
    #pragma unroll
    for (int i = 0; i < 4; i++) {
        ai[i][0] = sbi[cp];    ai[i][1] = sbi[cp+32];
        ao[i][0] = sbo[cp];    ao[i][1] = sbo[cp+32];
    }
    #pragma unroll 4
    for (int k = 0; k < 64; k++) {
        float wi0 = sWi[k*64 + cp], wi1 = sWi[k*64 + cp + 32];
        float wo0 = sWo[k*64 + cp], wo1 = sWo[k*64 + cp + 32];
        #pragma unroll
        for (int i = 0; i < 4; i++) {
            float hv = sh[(rg*4 + i)*65 + k];
            ai[i][0] += hv*wi0; ai[i][1] += hv*wi1;
            ao[i][0] += hv*wo0; ao[i][1] += hv*wo1;
        }
    }
    int chg = e*64 + nt;             // global chunk id 0..127
    int ks = chg >> 5, cc = chg & 31;
    #pragma unroll
    for (int io = 0; io < 2; io++) {
        __half* dst = g_msgT + ((size_t)((io*BB + b)*KSPL + ks))*65536 + cc*2048;
        float (*ac)[2] = io ? ao : ai;
        #pragma unroll
        for (int j = 0; j < 2; j++) {
            int d = cp + j*32;
            __half2 p0 = __floats2half2_rn(ac[0][j], ac[1][j]);
            __half2 p1 = __floats2half2_rn(ac[2][j], ac[3][j]);
            uint2 pk = make_uint2(*(uint32_t*)&p0, *(uint32_t*)&p1);
            *(uint2*)(dst + d*32 + rg*4) = pk;
        }
    }
}

// ---------------- GEMM fp16: 128 thr, 4 warps, warp tile 64x32, K-chunk 32, NSTG=4 ----------------
#define AROW 80
#define ASTG (128*AROW)            /* 10240 B */
#define BSTG (64*AROW)             /*  5120 B */
#define STGB (ASTG + BSTG)         /* 15360 B */
#define NSTG 4
#define SMEM_GEMM (NSTG*STGB)      /* 61440 B */

__global__ __launch_bounds__(128, 3) void k_gemm() {
    extern __shared__ char smc[];
    uint32_t usm = s2u(smc);
    int tid = threadIdx.x;
    int wid = tid >> 5, lane = tid & 31;
    int lr = lane >> 2, lc = lane & 3;
    int wm = wid & 1, wn = wid >> 1;       // 2x2 warp grid, warp tile 64x32
    int mt = blockIdx.x, dir = blockIdx.y;
    int b = blockIdx.z >> 2, ks = blockIdx.z & 3;
    int m0 = mt * 128;

    const __half* aBase = g_adjT + ((size_t)(((b*2 + dir)*KSPL + ks)*16 + mt))*TILEH;
    const __half* bBase = g_msgT + ((size_t)((dir*BB + b)*KSPL + ks))*65536;

    uint32_t aOff = (uint32_t)((wm*64 + (lane & 15))*AROW + (lane >> 4)*16);
    uint32_t bOff = (uint32_t)(ASTG + (wn*32 + ((lane >> 4)*8) + (lane & 7))*AROW + ((lane >> 3) & 1)*16);

    auto fill = [&](int stage, int c) {
        uint32_t ab = usm + stage*STGB;
        uint32_t bb = ab + ASTG;
        const __half* as = aBase + (size_t)c*4096;   // contiguous 8KB chunk
        const __half* bs = bBase + (size_t)c*2048;   // contiguous 4KB chunk
        #pragma unroll
        for (int i = 0; i < 4; i++) {
            int idx = tid + i*128;              // 512: r 0..127, q 0..3
            int r = idx >> 2, q = idx & 3;
            cpa16(ab + r*AROW + q*16, as + r*32 + q*8);
        }
        #pragma unroll
        for (int i = 0; i < 2; i++) {
            int idx = tid + i*128;              // 256: r 0..63, q 0..3
            int r = idx >> 2, q = idx & 3;
            cpa16(bb + r*AROW + q*16, bs + r*32 + q*8);
        }
        CPCOMMIT();
    };

    fill(0, 0);
    fill(1, 1);
    fill(2, 2);

    float acc[4][4][4];
    #pragma unroll
    for (int i = 0; i < 4; i++)
        #pragma unroll
        for (int j = 0; j < 4; j++)
            #pragma unroll
            for (int q = 0; q < 4; q++) acc[i][j][q] = 0.f;

    int st = 0;
    for (int c = 0; c < KCH; c++) {
        int rem = KCH - 1 - c;
        if (rem >= 2) CPWAIT(2); else if (rem == 1) CPWAIT(1); else CPWAIT(0);
        __syncthreads();
        if (c + 3 < KCH) {
            int s3 = st + 3; if (s3 >= NSTG) s3 -= NSTG;
            fill(s3, c + 3);
        }
        uint32_t ab = usm + st*STGB;
        #pragma unroll
        for (int k16 = 0; k16 < 2; k16++) {
            uint32_t af[4][4], bf[4][2];
            #pragma unroll
            for (int mf = 0; mf < 4; mf++)
                ldsm4(af[mf][0], af[mf][1], af[mf][2], af[mf][3],
                      ab + aOff + mf*(16*AROW) + k16*32);
            #pragma unroll
            for (int bg = 0; bg < 2; bg++) {
                uint32_t r0, r1, r2, r3;
                ldsm4(r0, r1, r2, r3, usm + st*STGB + bOff + bg*(16*AROW) + k16*32);
                bf[bg*2][0] = r0;   bf[bg*2][1] = r1;
                bf[bg*2+1][0] = r2; bf[bg*2+1][1] = r3;
            }
            #pragma unroll
            for (int mf = 0; mf < 4; mf++)
                #pragma unroll
                for (int nf = 0; nf < 4; nf++)
                    mma16(acc[mf][nf], af[mf], bf[nf]);
        }
        st = (st + 1 >= NSTG) ? 0 : st + 1;
    }

    float* dst = (dir ? g_aout : g_ain) + (size_t)ks*BB*NN*DD + (size_t)b*NN*64;
    #pragma unroll
    for (int mf = 0; mf < 4; mf++) {
        #pragma unroll
        for (int nf = 0; nf < 4; nf++) {
            int row = m0 + wm*64 + mf*16 + lr;
            int colg = wn*32 + nf*8 + lc*2;
            *(float2*)(dst + (size_t)row*64 + colg)     = make_float2(acc[mf][nf][0], acc[mf][nf][1]);
            *(float2*)(dst + (size_t)(row+8)*64 + colg) = make_float2(acc[mf][nf][2], acc[mf][nf][3]);
        }
    }
}

// ---------------- GRU: fp32 weights smem-staged; sums the K-split partials ----------------
#define GRU_WR 0
#define GRU_WZ 12288
#define GRU_WH 24576
#define GRU_SA 36864              /* 32*192 */
#define GRU_RH 43008              /* 32*64  */
#define SMEM_GRU ((GRU_RH + 2048)*4)   /* 180224 B */

__global__ __launch_bounds__(512, 1) void k_gru(
        const float* __restrict__ Wr, const float* __restrict__ br,
        const float* __restrict__ Wz, const float* __restrict__ bz,
        const float* __restrict__ Wh, const float* __restrict__ bh) {
    extern __shared__ float smf[];
    int nt = blockIdx.x, b = blockIdx.y;
    int tid = threadIdx.x;
    int n0 = nt * 32;

    #pragma unroll
    for (int i = 0; i < 6; i++) {
        int idx = tid + i*512;
        ((float4*)(smf + GRU_WR))[idx] = ((const float4*)Wr)[idx];
        ((float4*)(smf + GRU_WZ))[idx] = ((const float4*)Wz)[idx];
        ((float4*)(smf + GRU_WH))[idx] = ((const float4*)Wh)[idx];
    }
    const float* ain0  = g_ain  + (size_t)(b*NN + n0)*64;
    const float* aout0 = g_aout + (size_t)(b*NN + n0)*64;
    const float* hp    = g_h    + (size_t)(b*NN + n0)*64;
    const size_t PSTR = (size_t)BB*NN*DD;
    #pragma unroll
    for (int i = 0; i < 4; i++) {
        int idx = tid + i*512;
        int r = idx >> 6, c = idx & 63;
        float si = 0.f, so = 0.f;
        #pragma unroll
        for (int p = 0; p < KSPL; p++) {
            si += ain0[p*PSTR + r*64 + c];
            so += aout0[p*PSTR + r*64 + c];
        }
        smf[GRU_SA + r*192 + c]       = si;
        smf[GRU_SA + r*192 + 64 + c]  = so;
        smf[GRU_SA + r*192 + 128 + c] = hp[r*64 + c];
    }
    __syncthreads();

    int col = tid & 63, rg = tid >> 6;
    const float* sa = smf + GRU_SA;
    float accR[4], accZ[4];
    #pragma unroll
    for (int i = 0; i < 4; i++) { accR[i] = br[col]; accZ[i] = bz[col]; }
    #pragma unroll 8
    for (int k = 0; k < 192; k++) {
        float wr = smf[GRU_WR + k*64 + col];
        float wz = smf[GRU_WZ + k*64 + col];
        #pragma unroll
        for (int i = 0; i < 4; i++) {
            float v = sa[(rg*4 + i)*192 + k];
            accR[i] += v*wr; accZ[i] += v*wz;
        }
    }
    float zg[4], hold[4];
    #pragma unroll
    for (int i = 0; i < 4; i++) {
        int r = rg*4 + i;
        float rr = sigf(accR[i]);
        zg[i] = sigf(accZ[i]);
        hold[i] = sa[r*192 + 128 + col];
        smf[GRU_RH + r*64 + col] = rr * hold[i];
    }
    __syncthreads();

    float accH[4];
    #pragma unroll
    for (int i = 0; i < 4; i++) accH[i] = bh[col];
    #pragma unroll 8
    for (int k = 0; k < 128; k++) {
        float wh = smf[GRU_WH + k*64 + col];
        #pragma unroll
        for (int i = 0; i < 4; i++) accH[i] += sa[(rg*4 + i)*192 + k]*wh;
    }
    #pragma unroll 8
    for (int k = 0; k < 64; k++) {
        float wh = smf[GRU_WH + (128 + k)*64 + col];
        #pragma unroll
        for (int i = 0; i < 4; i++) accH[i] += smf[GRU_RH + (rg*4 + i)*64 + k]*wh;
    }
    float* hw = g_h + (size_t)(b*NN + n0)*64;
    #pragma unroll
    for (int i = 0; i < 4; i++) {
        int r = rg*4 + i;
        float hh = tanhf(accH[i]);
        hw[r*64 + col] = (1.0f - zg[i])*hold[i] + zg[i]*hh;
    }
}

// ---------------- readout ----------------
__global__ void k_out(const float* __restrict__ ann, const float* __restrict__ Wo1,
                      const float* __restrict__ bo1, const float* __restrict__ Wo2,
                      const float* __restrict__ bo2, float* __restrict__ out) {
    __shared__ float sx[4][80];
    __shared__ float sred[128];
    int blk = blockIdx.x;
    int b = blk >> 9;
    int n0 = (blk & 511) * 4;
    int tid = threadIdx.x;
    for (int i = tid; i < 256; i += 128) {
        int r = i >> 6, c = i & 63;
        sx[r][c] = g_h[(b*NN + n0 + r)*64 + c];
    }
    if (tid < 64) {
        int r = tid >> 4, c = tid & 15;
        sx[r][64 + c] = ann[(b*NN + n0 + r)*AAN + c];
    }
    __syncthreads();
    float v[4];
    float w2 = Wo2[tid], b1 = bo1[tid];
    #pragma unroll
    for (int r = 0; r < 4; r++) {
        float acc = b1;
        #pragma unroll 10
        for (int k = 0; k < 80; k++) acc += sx[r][k]*Wo1[k*128 + tid];
        v[r] = w2 * sigf(acc);
    }
    #pragma unroll
    for (int r = 0; r < 4; r++) {
        sred[tid] = v[r];
        __syncthreads();
        for (int s = 64; s > 0; s >>= 1) {
            if (tid < s) sred[tid] += sred[tid + s];
            __syncthreads();
        }
        if (tid == 0) out[b*NN + n0 + r] = sred[0] + bo2[0];
        __syncthreads();
    }
}

extern "C" void kernel_launch(void* const* d_in, const int* in_sizes, int n_in,
                              void* d_out, int out_size) {
    const float* prop = (const float*)d_in[0];
    const float* ann  = (const float*)d_in[1];
    const float* adj  = (const float*)d_in[2];
    const float* Win  = (const float*)d_in[3];
    const float* bin  = (const float*)d_in[4];
    const float* Wout = (const float*)d_in[5];
    const float* bout = (const float*)d_in[6];
    const float* Wr   = (const float*)d_in[7];
    const float* br   = (const float*)d_in[8];
    const float* Wz   = (const float*)d_in[9];
    const float* bz   = (const float*)d_in[10];
    const float* Wh   = (const float*)d_in[11];
    const float* bh   = (const float*)d_in[12];
    const float* Wo1  = (const float*)d_in[13];
    const float* bo1  = (const float*)d_in[14];
    const float* Wo2  = (const float*)d_in[15];
    const float* bo2  = (const float*)d_in[16];
    float* out = (float*)d_out;

    cudaFuncSetAttribute(k_gemm, cudaFuncAttributeMaxDynamicSharedMemorySize, SMEM_GEMM);
    cudaFuncSetAttribute(k_gru,  cudaFuncAttributeMaxDynamicSharedMemorySize, SMEM_GRU);

    k_init<<<256, 256>>>((const float4*)prop);
    k_roundT<<<dim3(16, 2, BB*KSPL), 256>>>(adj);
    for (int t = 0; t < TT; t++) {
        k_transform<<<dim3(64, EE, BB), 256>>>(Win, bin, Wout, bout);
        k_gemm<<<dim3(16, 2, BB*KSPL), 128, SMEM_GEMM>>>();
        k_gru<<<dim3(64, BB), 512, SMEM_GRU>>>(Wr, br, Wz, bz, Wh, bh);
    }
    k_out<<<1024, 128>>>(ann, Wo1, bo1, Wo2, bo2, out);
}